// round 17
// baseline (speedup 1.0000x reference)
#include <cuda_runtime.h>
#include <cstdint>

#define B   256
#define T   2048
#define HID 128
#define ATT 8

#define SPLIT 2                    // CTAs per batch
#define CHUNK (T / SPLIT)          // 1024 rows per CTA
#define NW 4                       // warps per CTA
#define THREADS (NW * 32)
#define ROWS_PER_WARP (CHUNK / NW) // 256
#define TR 8                       // rows per tile
#define NTILES (ROWS_PER_WARP / TR)// 32
#define TILE_F4 (TR * 32)          // 256 float4 per tile (4 KB)
#define NSTAGE 3
#define WBYTES (NSTAGE * TILE_F4 * 16)   // 12 KB per-warp buffer

__device__ float g_partial_v[B * SPLIT * HID];
__device__ float g_partial_s[B * SPLIT];
__device__ int   g_cnt[B];               // zero-init; winner resets

// H stream: read exactly once -> L2 evict-first.
__device__ __forceinline__ void cp_async16_ef(uint32_t dst, const void* src,
                                              uint64_t policy) {
    asm volatile("cp.async.cg.shared.global.L2::cache_hint [%0], [%1], 16, %2;\n"
                 :: "r"(dst), "l"(src), "l"(policy) : "memory");
}
__device__ __forceinline__ uint64_t mk_evict_first_policy() {
    uint64_t p;
    asm volatile("createpolicy.fractional.L2::evict_first.b64 %0, 1.0;\n" : "=l"(p));
    return p;
}
// Data that WILL be re-read by the winner epilogue -> L2 evict-last.
__device__ __forceinline__ uint64_t mk_evict_last_policy() {
    uint64_t p;
    asm volatile("createpolicy.fractional.L2::evict_last.b64 %0, 1.0;\n" : "=l"(p));
    return p;
}
__device__ __forceinline__ void st_el_f32(float* dst, float v, uint64_t policy) {
    asm volatile("st.global.L2::cache_hint.f32 [%0], %1, %2;\n"
                 :: "l"(dst), "f"(v), "l"(policy) : "memory");
}
__device__ __forceinline__ void cp_commit() {
    asm volatile("cp.async.commit_group;\n" ::: "memory");
}
template<int N> __device__ __forceinline__ void cp_wait() {
    asm volatile("cp.async.wait_group %0;\n" :: "n"(N) : "memory");
}
__device__ __forceinline__ uint32_t smem_u32(const void* p) {
    return (uint32_t)__cvta_generic_to_shared(p);
}

#define FULL 0xffffffffu

__global__ void __launch_bounds__(THREADS)
mata_main(const float* __restrict__ H,
          const float* __restrict__ mask,
          const float* __restrict__ Wt,
          const float* __restrict__ Wx,
          const float* __restrict__ rate,
          const float* __restrict__ obs_bias,
          const float* __restrict__ miss_bias,
          float* __restrict__ v_out,
          float* __restrict__ a_out)
{
    __shared__ __align__(16) char s_mem[NW * WBYTES];   // 48 KB tile buffers
    __shared__ float s_sred[NW];
    __shared__ float s_red[NW][ATT];
    __shared__ __align__(16) float s_p[HID];
    __shared__ int   s_last;

    const int bx   = blockIdx.x;
    const int b    = bx / SPLIT;
    const int c    = bx % SPLIT;
    const int tid  = threadIdx.x;
    const int wid  = tid >> 5;
    const int lane = tid & 31;

    const float* Hb = H + (size_t)b * T * HID;
    const int t0w = c * CHUNK + wid * ROWS_PER_WARP;

    float4* mybuf = (float4*)(s_mem + wid * WBYTES);
    const uint32_t mybuf_u = smem_u32(mybuf);
    const uint64_t pol_ef = mk_evict_first_policy();
    const uint64_t pol_el = mk_evict_last_policy();

    // ---- prologue: launch 3-tile prefetch immediately ----
    #pragma unroll
    for (int p = 0; p < NSTAGE; p++) {
        const float4* src = (const float4*)(Hb + (size_t)(t0w + p * TR) * HID);
        const uint32_t dbase = mybuf_u + p * TILE_F4 * 16;
        #pragma unroll
        for (int j = 0; j < TR; j++)
            cp_async16_ef(dbase + (j * 32 + lane) * 16, src + j * 32 + lane, pol_ef);
        cp_commit();
    }

    // ---- fused q/p computation (overlaps with prefetch in flight) ----
    {
        const float  hl  = __ldg(Hb + (size_t)(T - 1) * HID + tid);
        const float4 wt0 = __ldg((const float4*)(Wt + tid * ATT));
        const float4 wt1 = __ldg((const float4*)(Wt + tid * ATT) + 1);
        float qa[ATT];
        qa[0] = hl * wt0.x; qa[1] = hl * wt0.y; qa[2] = hl * wt0.z; qa[3] = hl * wt0.w;
        qa[4] = hl * wt1.x; qa[5] = hl * wt1.y; qa[6] = hl * wt1.z; qa[7] = hl * wt1.w;
        #pragma unroll
        for (int off = 16; off > 0; off >>= 1) {
            #pragma unroll
            for (int a = 0; a < ATT; a++)
                qa[a] += __shfl_xor_sync(FULL, qa[a], off);
        }
        if (lane == 0) {
            #pragma unroll
            for (int a = 0; a < ATT; a++) s_red[wid][a] = qa[a];
        }
        __syncthreads();
        float q[ATT];
        #pragma unroll
        for (int a = 0; a < ATT; a++)
            q[a] = s_red[0][a] + s_red[1][a] + s_red[2][a] + s_red[3][a];
        const float4 wx0 = __ldg((const float4*)(Wx + tid * ATT));
        const float4 wx1 = __ldg((const float4*)(Wx + tid * ATT) + 1);
        s_p[tid] = wx0.x * q[0] + wx0.y * q[1] + wx0.z * q[2] + wx0.w * q[3]
                 + wx1.x * q[4] + wx1.y * q[5] + wx1.z * q[6] + wx1.w * q[7];
        __syncthreads();
    }
    const float4 pv = ((const float4*)s_p)[lane];

    const float sr = 1.f / (1.f + __expf(-__ldg(rate)));
    const float ob = __ldg(obs_bias);
    const float mb = __ldg(miss_bias);

    const float* __restrict__ mrow = mask + (size_t)b * T;
    float* __restrict__ arow = a_out + (size_t)b * T;

    const int vrow = (lane >> 2) & 7;

    float4 acc  = make_float4(0.f, 0.f, 0.f, 0.f);
    float  sumw = 0.f;
    int slot = 0;

    #pragma unroll 1
    for (int kt = 0; kt < NTILES; kt++) {
        const int tbase = t0w + kt * TR;
        const float m = __ldcs(mrow + tbase + vrow);   // read once: streaming load

        cp_wait<2>();   // tile kt resident, two more in flight

        const float4* buf = mybuf + slot * TILE_F4;

        float4 tv[TR];
        #pragma unroll
        for (int j = 0; j < TR; j++) tv[j] = buf[j * 32 + lane];

        float d[TR];
        #pragma unroll
        for (int j = 0; j < TR; j++)
            d[j] = tv[j].x * pv.x + tv[j].y * pv.y + tv[j].z * pv.z + tv[j].w * pv.w;

        if (kt + NSTAGE < NTILES) {
            const float4* src = (const float4*)(Hb + (size_t)(t0w + (kt + NSTAGE) * TR) * HID);
            const uint32_t dbase = mybuf_u + slot * TILE_F4 * 16;
            #pragma unroll
            for (int j = 0; j < TR; j++)
                cp_async16_ef(dbase + (j * 32 + lane) * 16, src + j * 32 + lane, pol_ef);
            cp_commit();
        }

        // value-halving cross-lane reduction: 9 shuffles
        const bool hi16 = (lane & 16) != 0;
        float e[4];
        #pragma unroll
        for (int j = 0; j < 4; j++) {
            float x = hi16 ? d[j] : d[j + 4];
            float r = __shfl_xor_sync(FULL, x, 16);
            e[j] = (hi16 ? d[j + 4] : d[j]) + r;
        }
        const bool hi8 = (lane & 8) != 0;
        float f[2];
        #pragma unroll
        for (int j = 0; j < 2; j++) {
            float x = hi8 ? e[j] : e[j + 2];
            float r = __shfl_xor_sync(FULL, x, 8);
            f[j] = (hi8 ? e[j + 2] : e[j]) + r;
        }
        const bool hi4 = (lane & 4) != 0;
        {
            float x = hi4 ? f[0] : f[1];
            float r = __shfl_xor_sync(FULL, x, 4);
            f[0] = (hi4 ? f[1] : f[0]) + r;
        }
        f[0] += __shfl_xor_sync(FULL, f[0], 1);
        f[0] += __shfl_xor_sync(FULL, f[0], 2);

        const int t = tbase + vrow;
        const float s   = 1.f / (1.f + __expf(-f[0]));
        const float bt  = (float)(T - t);
        const float den = sr * (__logf(2.72f + (1.f - s)) * bt);
        const float e2  = fmaxf(s / den, 0.f);
        const float w   = __expf(e2 + (m > 0.5f ? ob : mb));

        if ((lane & 3) == 0) st_el_f32(arow + t, w, pol_el);   // re-read by winner: pin in L2

        #pragma unroll
        for (int r2 = 0; r2 < TR; r2++) {
            const float wr = __shfl_sync(FULL, w, r2 << 2);
            acc.x += wr * tv[r2].x; acc.y += wr * tv[r2].y;
            acc.z += wr * tv[r2].z; acc.w += wr * tv[r2].w;
            sumw  += wr;
        }

        slot = (slot == NSTAGE - 1) ? 0 : slot + 1;
    }

    // ---- CTA reduction (vred overlays dead tile buffers) ----
    cp_wait<0>();
    __syncwarp();
    ((float4*)(s_mem + wid * WBYTES))[lane] = acc;
    if (lane == 0) s_sred[wid] = sumw;
    __syncthreads();

    if (tid < HID) {
        float v = 0.f;
        #pragma unroll
        for (int w = 0; w < NW; w++)
            v += ((float*)(s_mem + w * WBYTES))[tid];
        st_el_f32(&g_partial_v[((size_t)b * SPLIT + c) * HID + tid], v, pol_el);
    }
    if (tid == 0) {
        float ss = 0.f;
        #pragma unroll
        for (int w = 0; w < NW; w++) ss += s_sred[w];
        st_el_f32(&g_partial_s[b * SPLIT + c], ss, pol_el);
    }

    // ---- fused epilogue: last CTA of this batch normalizes ----
    __threadfence();
    __syncthreads();
    if (tid == 0) {
        int old = atomicAdd(&g_cnt[b], 1);
        s_last = (old == SPLIT - 1) ? 1 : 0;
    }
    __syncthreads();
    if (!s_last) return;
    __threadfence();

    float ss = 0.f;
    #pragma unroll
    for (int cc = 0; cc < SPLIT; cc++) ss += g_partial_s[b * SPLIT + cc];
    const float inv = 1.f / ss;

    if (tid < HID) {
        float v = 0.f;
        #pragma unroll
        for (int cc = 0; cc < SPLIT; cc++)
            v += g_partial_v[((size_t)b * SPLIT + cc) * HID + tid];
        v_out[(size_t)b * HID + tid] = v * inv;
    }

    float4* ab4 = (float4*)arow;
    #pragma unroll
    for (int i = tid; i < T / 4; i += THREADS) {
        float4 x = ab4[i];
        x.x *= inv; x.y *= inv; x.z *= inv; x.w *= inv;
        ab4[i] = x;
    }

    if (tid == 0) g_cnt[b] = 0;   // reset for next graph replay
}

extern "C" void kernel_launch(void* const* d_in, const int* in_sizes, int n_in,
                              void* d_out, int out_size)
{
    const float* H   = (const float*)d_in[0];
    const float* msk = (const float*)d_in[1];
    const float* Wt  = (const float*)d_in[2];
    const float* Wx  = (const float*)d_in[3];
    const float* rt  = (const float*)d_in[4];
    const float* ob  = (const float*)d_in[5];
    const float* mb  = (const float*)d_in[6];

    float* v_out = (float*)d_out;               // [B, HID]
    float* a_out = (float*)d_out + B * HID;     // [B, T]

    mata_main<<<B * SPLIT, THREADS>>>(H, msk, Wt, Wx, rt, ob, mb, v_out, a_out);
}